// round 15
// baseline (speedup 1.0000x reference)
#include <cuda_runtime.h>
#include <math.h>

#define KK 16
#define CC 8
#define TILE 128
#define NKC 136            // C + K*C output channels
#define PKSTRIDE 64        // padded per-k param record (floats)

// Packed per-k params: [0..7]=bias b=-Linv*mu, [8]=c2, [9..11]=pad,
// [12 + rowf4[i]*4 + j] = Linv[i][j] (row i padded to float4 boundary).
__device__ float g_pk[KK * PKSTRIDE];

// Column-parallel prep: thread = (k, column j) — proven R9 version.
__global__ void prep_kernel(const float* __restrict__ scale,
                            const float* __restrict__ mean) {
    const int tid = threadIdx.x;       // 0..127
    const int k = tid >> 3, j = tid & 7;
    const float* L = scale + k * 64;   // lower-triangular 8x8, row-major
    float* pk = g_pk + k * PKSTRIDE;

    float Lv[8][8];
    #pragma unroll
    for (int i = 0; i < 8; i++)
        #pragma unroll
        for (int m = 0; m <= i; m++)
            Lv[i][m] = L[i * 8 + m];

    float dj = L[j * 9];               // L[j][j]
    float rj = __frcp_rn(dj);
    float rinv[8];
    #pragma unroll
    for (int i = 0; i < 8; i++)
        rinv[i] = __shfl_sync(0xffffffffu, rj, i, 8);

    float lg = __logf(fabsf(dj));
    lg += __shfl_xor_sync(0xffffffffu, lg, 1, 8);
    lg += __shfl_xor_sync(0xffffffffu, lg, 2, 8);
    lg += __shfl_xor_sync(0xffffffffu, lg, 4, 8);   // logdet, all lanes

    float c[8];
    #pragma unroll
    for (int i = 0; i < 8; i++) {
        float s = (i == j) ? 1.f : 0.f;
        #pragma unroll
        for (int m = 0; m < i; m++)
            s = fmaf(-Lv[i][m], c[m], s);
        c[i] = (i >= j) ? s * rinv[i] : 0.f;
    }

    // Store ONLY lower-triangle slots (j <= i): disjoint addresses (R8 race).
    #pragma unroll
    for (int i = 0; i < 8; i++) {
        const int rowf4 = (i <= 4) ? i : 2 * i - 4;
        if (j <= i)
            pk[12 + rowf4 * 4 + j] = c[i];
    }

    // bias_i = -sum_j Linv[i][j]*mu[j]: per-row reduction across the group.
    float muj = mean[k * 8 + j];
    #pragma unroll
    for (int i = 0; i < 8; i++) {
        float p = c[i] * muj;
        p += __shfl_xor_sync(0xffffffffu, p, 1, 8);
        p += __shfl_xor_sync(0xffffffffu, p, 2, 8);
        p += __shfl_xor_sync(0xffffffffu, p, 4, 8);
        if (j == i) pk[i] = -p;
    }

    if (j == 0) {
        const float LN2PI = 1.8378770664093453f;
        const float LOG2E = 1.4426950408889634f;
        pk[8] = (-lg - 4.0f * LN2PI) * LOG2E;  // gauss = 2^(-0.5*log2e*quad + c2)
    }
}

// Occupancy push: min 10 blocks/SM (<=51 regs). The kernel is latency-bound
// (no pipe >60%, occ 45%) — extra resident warps cover LDS/LDG latency.
__global__ __launch_bounds__(128, 10)
void main_kernel(const float* __restrict__ x, float* __restrict__ out) {
    __shared__ float sPk[KK * PKSTRIDE];   // 4 KB
    __shared__ float xsT[8][TILE];         // 4 KB channel-major x tile

    const int tid = threadIdx.x;
    const int T   = blockIdx.x;            // 4096 tiles of 128 pixels
    const int bi  = T >> 9;                // image index
    const int tin = T & 511;               // tile within image
    const int sp  = T * TILE + tid;        // this thread's staging pixel

    // Prep-independent work FIRST (overlaps with prep under PDL):
    // coalesced pixel load, channel-major staging, identity copy.
    const float4* xp = reinterpret_cast<const float4*>(x + (long)sp * 8);
    float4 a = xp[0], b4 = xp[1];
    xsT[0][tid] = a.x;  xsT[1][tid] = a.y;
    xsT[2][tid] = a.z;  xsT[3][tid] = a.w;
    xsT[4][tid] = b4.x; xsT[5][tid] = b4.y;
    xsT[6][tid] = b4.z; xsT[7][tid] = b4.w;
    float4* op = reinterpret_cast<float4*>(out + (long)sp * NKC);
    op[0] = a;
    op[1] = b4;

    // Wait for prep_kernel's completion (PDL); its g_pk writes are visible.
    cudaGridDependencySynchronize();

    for (int i = tid; i < KK * PKSTRIDE; i += 128) sPk[i] = g_pk[i];
    __syncthreads();

    // Each warp owns 4 mixture components; each thread owns the 4 tile-local
    // pixels (lane*4 .. lane*4+3) that it will store.
    const int warp = tid >> 5, lane = tid & 31;

    float xcc[8][4];                       // x[channel][owned pixel]
    #pragma unroll
    for (int c = 0; c < 8; c++) {
        float4 v = *reinterpret_cast<const float4*>(&xsT[c][lane * 4]);
        xcc[c][0] = v.x; xcc[c][1] = v.y; xcc[c][2] = v.z; xcc[c][3] = v.w;
    }

    const float NH_LOG2E = -0.7213475204444817f;   // -0.5*log2(e)
    const int obase = tin * NKC + 8 + lane * 4;

    #pragma unroll 1
    for (int kk = 0; kk < 4; kk++) {
        const int k = warp * 4 + kk;
        const float* pk = &sPk[k * PKSTRIDE];
        #define LD4(o) (*reinterpret_cast<const float4*>(pk + (o)))
        float4 bA = LD4(0), bB = LD4(4);
        float c2 = LD4(8).x;
        float quad[4], y[4];
        float4 r, s;

        r = LD4(12);
        #pragma unroll
        for (int u = 0; u < 4; u++) {
            y[u] = fmaf(r.x, xcc[0][u], bA.x);
            quad[u] = y[u] * y[u];
        }
        r = LD4(16);
        #pragma unroll
        for (int u = 0; u < 4; u++) {
            y[u] = fmaf(r.y, xcc[1][u], fmaf(r.x, xcc[0][u], bA.y));
            quad[u] = fmaf(y[u], y[u], quad[u]);
        }
        r = LD4(20);
        #pragma unroll
        for (int u = 0; u < 4; u++) {
            y[u] = fmaf(r.z, xcc[2][u], fmaf(r.y, xcc[1][u],
                   fmaf(r.x, xcc[0][u], bA.z)));
            quad[u] = fmaf(y[u], y[u], quad[u]);
        }
        r = LD4(24);
        #pragma unroll
        for (int u = 0; u < 4; u++) {
            y[u] = fmaf(r.w, xcc[3][u], fmaf(r.z, xcc[2][u],
                   fmaf(r.y, xcc[1][u], fmaf(r.x, xcc[0][u], bA.w))));
            quad[u] = fmaf(y[u], y[u], quad[u]);
        }
        r = LD4(28); s = LD4(32);
        #pragma unroll
        for (int u = 0; u < 4; u++) {
            y[u] = fmaf(s.x, xcc[4][u], fmaf(r.w, xcc[3][u],
                   fmaf(r.z, xcc[2][u], fmaf(r.y, xcc[1][u],
                   fmaf(r.x, xcc[0][u], bB.x)))));
            quad[u] = fmaf(y[u], y[u], quad[u]);
        }
        r = LD4(36); s = LD4(40);
        #pragma unroll
        for (int u = 0; u < 4; u++) {
            y[u] = fmaf(s.y, xcc[5][u], fmaf(s.x, xcc[4][u],
                   fmaf(r.w, xcc[3][u], fmaf(r.z, xcc[2][u],
                   fmaf(r.y, xcc[1][u], fmaf(r.x, xcc[0][u], bB.y))))));
            quad[u] = fmaf(y[u], y[u], quad[u]);
        }
        r = LD4(44); s = LD4(48);
        #pragma unroll
        for (int u = 0; u < 4; u++) {
            y[u] = fmaf(s.z, xcc[6][u], fmaf(s.y, xcc[5][u],
                   fmaf(s.x, xcc[4][u], fmaf(r.w, xcc[3][u],
                   fmaf(r.z, xcc[2][u], fmaf(r.y, xcc[1][u],
                   fmaf(r.x, xcc[0][u], bB.z)))))));
            quad[u] = fmaf(y[u], y[u], quad[u]);
        }
        r = LD4(52); s = LD4(56);
        #pragma unroll
        for (int u = 0; u < 4; u++) {
            y[u] = fmaf(s.w, xcc[7][u], fmaf(s.z, xcc[6][u],
                   fmaf(s.y, xcc[5][u], fmaf(s.x, xcc[4][u],
                   fmaf(r.w, xcc[3][u], fmaf(r.z, xcc[2][u],
                   fmaf(r.y, xcc[1][u], fmaf(r.x, xcc[0][u], bB.w))))))));
            quad[u] = fmaf(y[u], y[u], quad[u]);
        }
        #undef LD4

        float g[4];
        #pragma unroll
        for (int u = 0; u < 4; u++) {
            float t = fmaf(quad[u], NH_LOG2E, c2);
            t = fmaxf(t, -120.f);
            float fi = rintf(t);
            float f  = t - fi;                 // [-0.5, 0.5]
            float p  = fmaf(f, 0.0013333558f, 0.0096181291f);
            p = fmaf(f, p, 0.0555041087f);
            p = fmaf(f, p, 0.2402265070f);
            p = fmaf(f, p, 0.6931471806f);
            p = fmaf(f, p, 1.0f);
            float sc = __int_as_float(((int)fi + 127) << 23);  // 2^fi
            g[u] = p * sc;
        }

        // Store 8 channel-segments for this k: contiguous, coalesced 512 B
        // runs: out[(seg*8+bi)*512*NKC + tin*NKC + 8 + lane*4].
        #pragma unroll
        for (int c = 0; c < 8; c++) {
            int seg = k * 8 + c;
            int A = (seg * 8 + bi) * (512 * NKC) + obase;   // < 2^31
            float4 o;
            o.x = g[0] * xcc[c][0];
            o.y = g[1] * xcc[c][1];
            o.z = g[2] * xcc[c][2];
            o.w = g[3] * xcc[c][3];
            *reinterpret_cast<float4*>(out + A) = o;
        }
    }
}

extern "C" void kernel_launch(void* const* d_in, const int* in_sizes, int n_in,
                              void* d_out, int out_size) {
    // Identify inputs by element count: x=4,194,304; scale=1,024; mean=128
    const float* x = nullptr; const float* scale = nullptr; const float* mean = nullptr;
    for (int i = 0; i < n_in; i++) {
        if (in_sizes[i] == 4194304)      x     = (const float*)d_in[i];
        else if (in_sizes[i] == 1024)    scale = (const float*)d_in[i];
        else if (in_sizes[i] == 128)     mean  = (const float*)d_in[i];
    }
    float* out = (float*)d_out;

    prep_kernel<<<1, 128>>>(scale, mean);

    // PDL: main launches while prep is still running; main's blocks do their
    // prep-independent x-load/identity-copy, then wait at
    // cudaGridDependencySynchronize() for prep completion.
    cudaLaunchConfig_t cfg = {};
    cfg.gridDim  = dim3(4096, 1, 1);
    cfg.blockDim = dim3(128, 1, 1);
    cfg.dynamicSmemBytes = 0;
    cfg.stream = 0;                        // same (legacy) stream as <<<>>>
    cudaLaunchAttribute attrs[1];
    attrs[0].id = cudaLaunchAttributeProgrammaticStreamSerialization;
    attrs[0].val.programmaticStreamSerializationAllowed = 1;
    cfg.attrs = attrs;
    cfg.numAttrs = 1;
    cudaLaunchKernelEx(&cfg, main_kernel, x, out);
}

// round 16
// speedup vs baseline: 1.2036x; 1.2036x over previous
#include <cuda_runtime.h>
#include <math.h>

#define KK 16
#define CC 8
#define TILE 128
#define NKC 136            // C + K*C output channels
#define PKSTRIDE 64        // padded per-k param record (floats)

// Packed per-k params: [0..7]=bias b=-Linv*mu, [8]=c2, [9..11]=pad,
// [12 + rowf4[i]*4 + j] = Linv[i][j] (row i padded to float4 boundary).
__device__ float g_pk[KK * PKSTRIDE];

// Column-parallel prep: thread = (k, column j) — proven R9 version.
__global__ void prep_kernel(const float* __restrict__ scale,
                            const float* __restrict__ mean) {
    const int tid = threadIdx.x;       // 0..127
    const int k = tid >> 3, j = tid & 7;
    const float* L = scale + k * 64;   // lower-triangular 8x8, row-major
    float* pk = g_pk + k * PKSTRIDE;

    float Lv[8][8];
    #pragma unroll
    for (int i = 0; i < 8; i++)
        #pragma unroll
        for (int m = 0; m <= i; m++)
            Lv[i][m] = L[i * 8 + m];

    float dj = L[j * 9];               // L[j][j]
    float rj = __frcp_rn(dj);
    float rinv[8];
    #pragma unroll
    for (int i = 0; i < 8; i++)
        rinv[i] = __shfl_sync(0xffffffffu, rj, i, 8);

    float lg = __logf(fabsf(dj));
    lg += __shfl_xor_sync(0xffffffffu, lg, 1, 8);
    lg += __shfl_xor_sync(0xffffffffu, lg, 2, 8);
    lg += __shfl_xor_sync(0xffffffffu, lg, 4, 8);   // logdet, all lanes

    float c[8];
    #pragma unroll
    for (int i = 0; i < 8; i++) {
        float s = (i == j) ? 1.f : 0.f;
        #pragma unroll
        for (int m = 0; m < i; m++)
            s = fmaf(-Lv[i][m], c[m], s);
        c[i] = (i >= j) ? s * rinv[i] : 0.f;
    }

    // Store ONLY lower-triangle slots (j <= i): disjoint addresses (R8 race).
    #pragma unroll
    for (int i = 0; i < 8; i++) {
        const int rowf4 = (i <= 4) ? i : 2 * i - 4;
        if (j <= i)
            pk[12 + rowf4 * 4 + j] = c[i];
    }

    // bias_i = -sum_j Linv[i][j]*mu[j]: per-row reduction across the group.
    float muj = mean[k * 8 + j];
    #pragma unroll
    for (int i = 0; i < 8; i++) {
        float p = c[i] * muj;
        p += __shfl_xor_sync(0xffffffffu, p, 1, 8);
        p += __shfl_xor_sync(0xffffffffu, p, 2, 8);
        p += __shfl_xor_sync(0xffffffffu, p, 4, 8);
        if (j == i) pk[i] = -p;
    }

    if (j == 0) {
        const float LN2PI = 1.8378770664093453f;
        const float LOG2E = 1.4426950408889634f;
        pk[8] = (-lg - 4.0f * LN2PI) * LOG2E;  // gauss = 2^(-0.5*log2e*quad + c2)
    }
}

// R12 configuration (8 blocks/SM optimum, 64 regs) + streaming stores:
// all output is write-once/never-read -> evict-first policy keeps L2 clean.
__global__ __launch_bounds__(128)
void main_kernel(const float* __restrict__ x, float* __restrict__ out) {
    __shared__ float sPk[KK * PKSTRIDE];   // 4 KB
    __shared__ float xsT[8][TILE];         // 4 KB channel-major x tile

    const int tid = threadIdx.x;
    const int T   = blockIdx.x;            // 4096 tiles of 128 pixels
    const int bi  = T >> 9;                // image index
    const int tin = T & 511;               // tile within image
    const int sp  = T * TILE + tid;        // this thread's staging pixel

    // Prep-independent work FIRST (overlaps with prep under PDL):
    // coalesced pixel load, channel-major staging, identity copy.
    const float4* xp = reinterpret_cast<const float4*>(x + (long)sp * 8);
    float4 a = xp[0], b4 = xp[1];
    xsT[0][tid] = a.x;  xsT[1][tid] = a.y;
    xsT[2][tid] = a.z;  xsT[3][tid] = a.w;
    xsT[4][tid] = b4.x; xsT[5][tid] = b4.y;
    xsT[6][tid] = b4.z; xsT[7][tid] = b4.w;
    float4* op = reinterpret_cast<float4*>(out + (long)sp * NKC);
    __stcs(op,     a);
    __stcs(op + 1, b4);

    // Wait for prep_kernel's completion (PDL); its g_pk writes are visible.
    cudaGridDependencySynchronize();

    for (int i = tid; i < KK * PKSTRIDE; i += 128) sPk[i] = g_pk[i];
    __syncthreads();

    // Each warp owns 4 mixture components; each thread owns the 4 tile-local
    // pixels (lane*4 .. lane*4+3) that it will store.
    const int warp = tid >> 5, lane = tid & 31;

    float xcc[8][4];                       // x[channel][owned pixel]
    #pragma unroll
    for (int c = 0; c < 8; c++) {
        float4 v = *reinterpret_cast<const float4*>(&xsT[c][lane * 4]);
        xcc[c][0] = v.x; xcc[c][1] = v.y; xcc[c][2] = v.z; xcc[c][3] = v.w;
    }

    const float NH_LOG2E = -0.7213475204444817f;   // -0.5*log2(e)
    const int obase = tin * NKC + 8 + lane * 4;

    #pragma unroll 1
    for (int kk = 0; kk < 4; kk++) {
        const int k = warp * 4 + kk;
        const float* pk = &sPk[k * PKSTRIDE];
        #define LD4(o) (*reinterpret_cast<const float4*>(pk + (o)))
        float4 bA = LD4(0), bB = LD4(4);
        float c2 = LD4(8).x;
        float quad[4], y[4];
        float4 r, s;

        r = LD4(12);
        #pragma unroll
        for (int u = 0; u < 4; u++) {
            y[u] = fmaf(r.x, xcc[0][u], bA.x);
            quad[u] = y[u] * y[u];
        }
        r = LD4(16);
        #pragma unroll
        for (int u = 0; u < 4; u++) {
            y[u] = fmaf(r.y, xcc[1][u], fmaf(r.x, xcc[0][u], bA.y));
            quad[u] = fmaf(y[u], y[u], quad[u]);
        }
        r = LD4(20);
        #pragma unroll
        for (int u = 0; u < 4; u++) {
            y[u] = fmaf(r.z, xcc[2][u], fmaf(r.y, xcc[1][u],
                   fmaf(r.x, xcc[0][u], bA.z)));
            quad[u] = fmaf(y[u], y[u], quad[u]);
        }
        r = LD4(24);
        #pragma unroll
        for (int u = 0; u < 4; u++) {
            y[u] = fmaf(r.w, xcc[3][u], fmaf(r.z, xcc[2][u],
                   fmaf(r.y, xcc[1][u], fmaf(r.x, xcc[0][u], bA.w))));
            quad[u] = fmaf(y[u], y[u], quad[u]);
        }
        r = LD4(28); s = LD4(32);
        #pragma unroll
        for (int u = 0; u < 4; u++) {
            y[u] = fmaf(s.x, xcc[4][u], fmaf(r.w, xcc[3][u],
                   fmaf(r.z, xcc[2][u], fmaf(r.y, xcc[1][u],
                   fmaf(r.x, xcc[0][u], bB.x)))));
            quad[u] = fmaf(y[u], y[u], quad[u]);
        }
        r = LD4(36); s = LD4(40);
        #pragma unroll
        for (int u = 0; u < 4; u++) {
            y[u] = fmaf(s.y, xcc[5][u], fmaf(s.x, xcc[4][u],
                   fmaf(r.w, xcc[3][u], fmaf(r.z, xcc[2][u],
                   fmaf(r.y, xcc[1][u], fmaf(r.x, xcc[0][u], bB.y))))));
            quad[u] = fmaf(y[u], y[u], quad[u]);
        }
        r = LD4(44); s = LD4(48);
        #pragma unroll
        for (int u = 0; u < 4; u++) {
            y[u] = fmaf(s.z, xcc[6][u], fmaf(s.y, xcc[5][u],
                   fmaf(s.x, xcc[4][u], fmaf(r.w, xcc[3][u],
                   fmaf(r.z, xcc[2][u], fmaf(r.y, xcc[1][u],
                   fmaf(r.x, xcc[0][u], bB.z)))))));
            quad[u] = fmaf(y[u], y[u], quad[u]);
        }
        r = LD4(52); s = LD4(56);
        #pragma unroll
        for (int u = 0; u < 4; u++) {
            y[u] = fmaf(s.w, xcc[7][u], fmaf(s.z, xcc[6][u],
                   fmaf(s.y, xcc[5][u], fmaf(s.x, xcc[4][u],
                   fmaf(r.w, xcc[3][u], fmaf(r.z, xcc[2][u],
                   fmaf(r.y, xcc[1][u], fmaf(r.x, xcc[0][u], bB.w))))))));
            quad[u] = fmaf(y[u], y[u], quad[u]);
        }
        #undef LD4

        float g[4];
        #pragma unroll
        for (int u = 0; u < 4; u++) {
            float t = fmaf(quad[u], NH_LOG2E, c2);
            t = fmaxf(t, -120.f);
            float fi = rintf(t);
            float f  = t - fi;                 // [-0.5, 0.5]
            float p  = fmaf(f, 0.0013333558f, 0.0096181291f);
            p = fmaf(f, p, 0.0555041087f);
            p = fmaf(f, p, 0.2402265070f);
            p = fmaf(f, p, 0.6931471806f);
            p = fmaf(f, p, 1.0f);
            float sc = __int_as_float(((int)fi + 127) << 23);  // 2^fi
            g[u] = p * sc;
        }

        // Store 8 channel-segments for this k: contiguous, coalesced 512 B
        // runs: out[(seg*8+bi)*512*NKC + tin*NKC + 8 + lane*4].
        #pragma unroll
        for (int c = 0; c < 8; c++) {
            int seg = k * 8 + c;
            int A = (seg * 8 + bi) * (512 * NKC) + obase;   // < 2^31
            float4 o;
            o.x = g[0] * xcc[c][0];
            o.y = g[1] * xcc[c][1];
            o.z = g[2] * xcc[c][2];
            o.w = g[3] * xcc[c][3];
            __stcs(reinterpret_cast<float4*>(out + A), o);
        }
    }
}

extern "C" void kernel_launch(void* const* d_in, const int* in_sizes, int n_in,
                              void* d_out, int out_size) {
    // Identify inputs by element count: x=4,194,304; scale=1,024; mean=128
    const float* x = nullptr; const float* scale = nullptr; const float* mean = nullptr;
    for (int i = 0; i < n_in; i++) {
        if (in_sizes[i] == 4194304)      x     = (const float*)d_in[i];
        else if (in_sizes[i] == 1024)    scale = (const float*)d_in[i];
        else if (in_sizes[i] == 128)     mean  = (const float*)d_in[i];
    }
    float* out = (float*)d_out;

    prep_kernel<<<1, 128>>>(scale, mean);

    // PDL: main launches while prep is still running; main's blocks do their
    // prep-independent x-load/identity-copy, then wait at
    // cudaGridDependencySynchronize() for prep completion.
    cudaLaunchConfig_t cfg = {};
    cfg.gridDim  = dim3(4096, 1, 1);
    cfg.blockDim = dim3(128, 1, 1);
    cfg.dynamicSmemBytes = 0;
    cfg.stream = 0;                        // same (legacy) stream as <<<>>>
    cudaLaunchAttribute attrs[1];
    attrs[0].id = cudaLaunchAttributeProgrammaticStreamSerialization;
    attrs[0].val.programmaticStreamSerializationAllowed = 1;
    cfg.attrs = attrs;
    cfg.numAttrs = 1;
    cudaLaunchKernelEx(&cfg, main_kernel, x, out);
}